// round 1
// baseline (speedup 1.0000x reference)
#include <cuda_runtime.h>

// Problem constants (fixed by the reference):
//   N=4096 samples, D=128 input dim, P=128 pe dim (== D), H=256 hidden.
#define NN 4096
#define DD 128
#define HH 256

// Scratch: base[n][h] = (x @ W1[:D])[n][h] + b1[h]
__device__ float g_base[NN * HH];

typedef unsigned long long u64;

__device__ __forceinline__ u64 pk2(float x, float y) {
    u64 r; asm("mov.b64 %0, {%1, %2};" : "=l"(r) : "f"(x), "f"(y)); return r;
}
__device__ __forceinline__ u64 fma2_(u64 a, u64 b, u64 c) {
    u64 d; asm("fma.rn.f32x2 %0, %1, %2, %3;" : "=l"(d) : "l"(a), "l"(b), "l"(c)); return d;
}
__device__ __forceinline__ u64 add2_(u64 a, u64 b) {
    u64 d; asm("add.rn.f32x2 %0, %1, %2;" : "=l"(d) : "l"(a), "l"(b)); return d;
}
__device__ __forceinline__ u64 relu2_(u64 a) {
    float x, y;
    asm("mov.b64 {%0, %1}, %2;" : "=f"(x), "=f"(y) : "l"(a));
    x = fmaxf(x, 0.0f); y = fmaxf(y, 0.0f);
    return pk2(x, y);
}
__device__ __forceinline__ float2 unpk(u64 a) {
    float2 v; asm("mov.b64 {%0, %1}, %2;" : "=f"(v.x), "=f"(v.y) : "l"(a)); return v;
}

// ---------------------------------------------------------------------------
// K1: base = x @ W1[:D] + b1   (4096 x 256, K=128)
// Tiles: 64(n) x 64(h) x 32(k); 256 threads; 4x4 register microtile.
// Also writes the leading ones column of the output (blockIdx.y == 0).
// ---------------------------------------------------------------------------
__global__ __launch_bounds__(256) void nimo_base_kernel(
    const float* __restrict__ x, const float* __restrict__ W1,
    const float* __restrict__ b1, float* __restrict__ out)
{
    __shared__ __align__(16) float xs[32][68];  // [k][n] transposed, padded
    __shared__ __align__(16) float ws[32][68];  // [k][h], padded

    const int tid = threadIdx.x;
    const int n0 = blockIdx.x * 64;
    const int h0 = blockIdx.y * 64;
    const int tx = tid & 15;   // h group (0..15) -> 4 h
    const int ty = tid >> 4;   // n group (0..15) -> 4 n

    float acc[4][4];
#pragma unroll
    for (int i = 0; i < 4; i++)
#pragma unroll
        for (int j = 0; j < 4; j++) acc[i][j] = 0.0f;

    for (int kt = 0; kt < DD; kt += 32) {
#pragma unroll
        for (int i = 0; i < 8; i++) {           // 64n x 32k = 2048 elems
            int e = tid + i * 256;
            int r = e >> 5, k = e & 31;
            xs[k][r] = x[(n0 + r) * DD + kt + k];
        }
#pragma unroll
        for (int i = 0; i < 8; i++) {           // 32k x 64h = 2048 elems
            int e = tid + i * 256;
            int k = e >> 6, c = e & 63;
            ws[k][c] = W1[(kt + k) * HH + h0 + c];
        }
        __syncthreads();
#pragma unroll
        for (int kk = 0; kk < 32; kk++) {
            float4 xv = *(const float4*)&xs[kk][ty * 4];
            float4 wv = *(const float4*)&ws[kk][tx * 4];
            acc[0][0] += xv.x * wv.x; acc[0][1] += xv.x * wv.y;
            acc[0][2] += xv.x * wv.z; acc[0][3] += xv.x * wv.w;
            acc[1][0] += xv.y * wv.x; acc[1][1] += xv.y * wv.y;
            acc[1][2] += xv.y * wv.z; acc[1][3] += xv.y * wv.w;
            acc[2][0] += xv.z * wv.x; acc[2][1] += xv.z * wv.y;
            acc[2][2] += xv.z * wv.z; acc[2][3] += xv.z * wv.w;
            acc[3][0] += xv.w * wv.x; acc[3][1] += xv.w * wv.y;
            acc[3][2] += xv.w * wv.z; acc[3][3] += xv.w * wv.w;
        }
        __syncthreads();
    }

    float4 bv = *(const float4*)&b1[h0 + tx * 4];
#pragma unroll
    for (int i = 0; i < 4; i++) {
        float4 o;
        o.x = acc[i][0] + bv.x; o.y = acc[i][1] + bv.y;
        o.z = acc[i][2] + bv.z; o.w = acc[i][3] + bv.w;
        *(float4*)&g_base[(n0 + ty * 4 + i) * HH + h0 + tx * 4] = o;
    }

    // ones column
    if (blockIdx.y == 0 && tid < 64) out[(n0 + tid) * (DD + 1)] = 1.0f;
}

// ---------------------------------------------------------------------------
// K2: per (n, j):
//   g = sum_h relu(base[n,h] + W1[D+j,h] - x[n,j]*W1[j,h]) * W2[h]
//   out[n, 1+j] = x[n,j] * (1 + b2 + g)
// Layout: block = 8 warps; warp owns 8 n (base in registers, packed f32x2);
// lanes split h (lane l -> h in {4l..4l+3} and {128+4l..131+4l});
// grid = (64 n-tiles, 4 j-tiles of 32). Barrier-free main loop; W1/pe rows
// hit L1 across the 8 warps of a block.
// ---------------------------------------------------------------------------
__global__ __launch_bounds__(256) void nimo_main_kernel(
    const float* __restrict__ x, const float* __restrict__ W1,
    const float* __restrict__ W2, const float* __restrict__ b2,
    float* __restrict__ out)
{
    const int lane = threadIdx.x & 31;
    const int warp = threadIdx.x >> 5;
    const int n_base = blockIdx.x * 64 + warp * 8;
    const int j_base = blockIdx.y * 32;
    const int hA = 4 * lane;        // 0..124
    const int hB = 128 + 4 * lane;  // 128..252

    // base for this warp's 8 n, this lane's 8 h, packed into f32x2 pairs
    u64 bA[8][2], bB[8][2];
#pragma unroll
    for (int i = 0; i < 8; i++) {
        float4 a = *(const float4*)&g_base[(n_base + i) * HH + hA];
        float4 b = *(const float4*)&g_base[(n_base + i) * HH + hB];
        bA[i][0] = pk2(a.x, a.y); bA[i][1] = pk2(a.z, a.w);
        bB[i][0] = pk2(b.x, b.y); bB[i][1] = pk2(b.z, b.w);
    }
    float4 w2a = *(const float4*)&W2[hA];
    float4 w2b = *(const float4*)&W2[hB];
    u64 w2p[4] = { pk2(w2a.x, w2a.y), pk2(w2a.z, w2a.w),
                   pk2(w2b.x, w2b.y), pk2(w2b.z, w2b.w) };
    const float b2v = b2[0];

    for (int jj = 0; jj < 32; jj++) {
        const int j = j_base + jj;
        float4 wA = *(const float4*)&W1[j * HH + hA];
        float4 wB = *(const float4*)&W1[j * HH + hB];
        float4 pA = *(const float4*)&W1[(DD + j) * HH + hA];
        float4 pB = *(const float4*)&W1[(DD + j) * HH + hB];
        u64 w1p[4] = { pk2(wA.x, wA.y), pk2(wA.z, wA.w),
                       pk2(wB.x, wB.y), pk2(wB.z, wB.w) };
        u64 pep[4] = { pk2(pA.x, pA.y), pk2(pA.z, pA.w),
                       pk2(pB.x, pB.y), pk2(pB.z, pB.w) };
#pragma unroll
        for (int i = 0; i < 8; i++) {
            const int n = n_base + i;
            const float xj = __ldg(&x[n * DD + j]);   // warp-uniform load
            const u64 nx2 = pk2(-xj, -xj);
            u64 acc = 0ull;  // {0.0f, 0.0f}
            u64 v;
            v = fma2_(nx2, w1p[0], pep[0]); v = add2_(v, bA[i][0]);
            v = relu2_(v); acc = fma2_(v, w2p[0], acc);
            v = fma2_(nx2, w1p[1], pep[1]); v = add2_(v, bA[i][1]);
            v = relu2_(v); acc = fma2_(v, w2p[1], acc);
            v = fma2_(nx2, w1p[2], pep[2]); v = add2_(v, bB[i][0]);
            v = relu2_(v); acc = fma2_(v, w2p[2], acc);
            v = fma2_(nx2, w1p[3], pep[3]); v = add2_(v, bB[i][1]);
            v = relu2_(v); acc = fma2_(v, w2p[3], acc);
            float2 ac = unpk(acc);
            float s = ac.x + ac.y;
            s += __shfl_xor_sync(0xffffffffu, s, 16);
            s += __shfl_xor_sync(0xffffffffu, s, 8);
            s += __shfl_xor_sync(0xffffffffu, s, 4);
            s += __shfl_xor_sync(0xffffffffu, s, 2);
            s += __shfl_xor_sync(0xffffffffu, s, 1);
            if (lane == 0) out[n * (DD + 1) + 1 + j] = xj * (1.0f + b2v + s);
        }
    }
}

extern "C" void kernel_launch(void* const* d_in, const int* in_sizes, int n_in,
                              void* d_out, int out_size)
{
    const float* x  = (const float*)d_in[0];
    const float* W1 = (const float*)d_in[1];
    const float* b1 = (const float*)d_in[2];
    const float* W2 = (const float*)d_in[3];
    const float* b2 = (const float*)d_in[4];
    float* out = (float*)d_out;

    // K1: base GEMM + ones column. grid: 64 n-tiles x 4 h-tiles.
    nimo_base_kernel<<<dim3(64, 4), 256>>>(x, W1, b1, out);
    // K2: masked-MLP evaluation. grid: 64 n-tiles x 4 j-tiles.
    nimo_main_kernel<<<dim3(64, 4), 256>>>(x, W1, W2, b2, out);
}